// round 17
// baseline (speedup 1.0000x reference)
#include <cuda_runtime.h>
#include <stdint.h>

// ---------------------------------------------------------------------------
// LJ edge-message passing:  out[n] = sum_{e: dst[e]=n} f(|dr_e|)*unit(dr_e) - 0.1*v[n]
// dr_e = x[dst[e]] - x[src[e]];  f(r)=4*s^6*(12 s^6-6)/rc, rc=max(r,0.1), s=1/rc
// ---------------------------------------------------------------------------

#define NMAX 100352          // >= 100000 nodes, multiple of 4
#define GAMMA 0.1f

// Device-global scratch (no allocations allowed in kernel_launch).
__device__ float4 g_xpad[NMAX];   // x padded to float4: 1-sector gathers
__device__ float4 g_acc[NMAX];    // accumulator (init = -gamma*v), red.v4 target
__device__ int    g_is64;         // index dtype flag (1 = int64, 0 = int32)

// --- prep: sniff idx dtype, pad x to float4, init acc = -gamma*v ------------
__global__ void prep_kernel(const float* __restrict__ x,
                            const float* __restrict__ v,
                            const void*  __restrict__ src,
                            int n, int n_edges) {
    int t = blockIdx.x * blockDim.x + threadIdx.x;

    if (t == 0) {
        // int64 data in-range [0,n) when read as int64; int32 data reinterpreted
        // as int64 yields huge/garbage values -> deterministic dtype sniff.
        const long long* p = (const long long*)src;
        int k = 64; if (2 * k > n_edges) k = n_edges / 2;
        int ok = 1;
        for (int i = 0; i < k; i++) {
            long long val = p[i];
            if (val < 0 || val >= (long long)n) { ok = 0; break; }
        }
        g_is64 = ok;
    }

    int i4 = t * 4;
    if (i4 >= n) return;

    if (i4 + 4 <= n) {
        const float4* xv = (const float4*)x + t * 3;
        float4 a = xv[0], b = xv[1], c = xv[2];
        g_xpad[i4 + 0] = make_float4(a.x, a.y, a.z, 0.f);
        g_xpad[i4 + 1] = make_float4(a.w, b.x, b.y, 0.f);
        g_xpad[i4 + 2] = make_float4(b.z, b.w, c.x, 0.f);
        g_xpad[i4 + 3] = make_float4(c.y, c.z, c.w, 0.f);

        const float4* vv = (const float4*)v + t * 3;
        float4 p0 = vv[0], p1 = vv[1], p2 = vv[2];
        g_acc[i4 + 0] = make_float4(-GAMMA * p0.x, -GAMMA * p0.y, -GAMMA * p0.z, 0.f);
        g_acc[i4 + 1] = make_float4(-GAMMA * p0.w, -GAMMA * p1.x, -GAMMA * p1.y, 0.f);
        g_acc[i4 + 2] = make_float4(-GAMMA * p1.z, -GAMMA * p1.w, -GAMMA * p2.x, 0.f);
        g_acc[i4 + 3] = make_float4(-GAMMA * p2.y, -GAMMA * p2.z, -GAMMA * p2.w, 0.f);
    } else {
        for (int i = i4; i < n; i++) {
            g_xpad[i] = make_float4(x[3*i], x[3*i+1], x[3*i+2], 0.f);
            g_acc[i]  = make_float4(-GAMMA*v[3*i], -GAMMA*v[3*i+1], -GAMMA*v[3*i+2], 0.f);
        }
    }
}

// --- per-edge force + vector-atomic scatter, 4 edges/thread -----------------
__global__ void __launch_bounds__(256) edge_kernel(
    const void* __restrict__ src_raw,
    const void* __restrict__ dst_raw,
    int n_edges)
{
    int t = blockIdx.x * blockDim.x + threadIdx.x;
    int base = t * 4;
    if (base >= n_edges) return;

    int s[4], d[4];
    if (base + 4 <= n_edges) {
        if (g_is64) {
            const longlong2* sp = (const longlong2*)src_raw;
            const longlong2* dp = (const longlong2*)dst_raw;
            longlong2 s0 = __ldcs(sp + 2*t), s1 = __ldcs(sp + 2*t + 1);
            longlong2 d0 = __ldcs(dp + 2*t), d1 = __ldcs(dp + 2*t + 1);
            s[0]=(int)s0.x; s[1]=(int)s0.y; s[2]=(int)s1.x; s[3]=(int)s1.y;
            d[0]=(int)d0.x; d[1]=(int)d0.y; d[2]=(int)d1.x; d[3]=(int)d1.y;
        } else {
            int4 si = __ldcs((const int4*)src_raw + t);
            int4 di = __ldcs((const int4*)dst_raw + t);
            s[0]=si.x; s[1]=si.y; s[2]=si.z; s[3]=si.w;
            d[0]=di.x; d[1]=di.y; d[2]=di.z; d[3]=di.w;
        }
    } else {
        #pragma unroll
        for (int i = 0; i < 4; i++) {
            int e = base + i;
            if (e < n_edges) {
                if (g_is64) {
                    s[i] = (int)((const long long*)src_raw)[e];
                    d[i] = (int)((const long long*)dst_raw)[e];
                } else {
                    s[i] = ((const int*)src_raw)[e];
                    d[i] = ((const int*)dst_raw)[e];
                }
            } else { s[i] = 0; d[i] = 0; }   // dr=0 -> msg=0 -> harmless RED
        }
    }

    // Batch the 8 gathers first for max memory-level parallelism.
    float4 xs[4], xd[4];
    #pragma unroll
    for (int i = 0; i < 4; i++) {
        xs[i] = __ldg(&g_xpad[s[i]]);
        xd[i] = __ldg(&g_xpad[d[i]]);
    }

    #pragma unroll
    for (int i = 0; i < 4; i++) {
        float dx = xd[i].x - xs[i].x;
        float dy = xd[i].y - xs[i].y;
        float dz = xd[i].z - xs[i].z;

        float r2 = dx*dx + dy*dy + dz*dz;
        float r  = sqrtf(r2);
        float rc = fmaxf(r, 0.1f);            // MIN_R clamp (force arg)
        float is = 1.0f / rc;                 // s = RC/rc, RC=1
        float s2 = is * is;
        float s6 = s2 * s2 * s2;
        float f  = 4.0f * s6 * (12.0f * s6 - 6.0f) * is;
        float coef = f / fmaxf(r, 1e-12f);    // normalize uses unclamped r

        asm volatile(
            "red.global.add.v4.f32 [%0], {%1, %2, %3, %4};"
            :: "l"(&g_acc[d[i]]),
               "f"(coef * dx), "f"(coef * dy), "f"(coef * dz), "f"(0.0f)
            : "memory");
    }
}

// --- finalize: repack acc (float4) -> out (packed float3) -------------------
__global__ void finalize_kernel(float* __restrict__ out, int n) {
    int t = blockIdx.x * blockDim.x + threadIdx.x;
    int i4 = t * 4;
    if (i4 >= n) return;

    if (i4 + 4 <= n) {
        float4 a0 = g_acc[i4 + 0];
        float4 a1 = g_acc[i4 + 1];
        float4 a2 = g_acc[i4 + 2];
        float4 a3 = g_acc[i4 + 3];
        float4* ov = (float4*)out + t * 3;
        ov[0] = make_float4(a0.x, a0.y, a0.z, a1.x);
        ov[1] = make_float4(a1.y, a1.z, a2.x, a2.y);
        ov[2] = make_float4(a2.z, a3.x, a3.y, a3.z);
    } else {
        for (int i = i4; i < n; i++) {
            float4 a = g_acc[i];
            out[3*i + 0] = a.x;
            out[3*i + 1] = a.y;
            out[3*i + 2] = a.z;
        }
    }
}

extern "C" void kernel_launch(void* const* d_in, const int* in_sizes, int n_in,
                              void* d_out, int out_size) {
    const float* x   = (const float*)d_in[0];
    const float* v   = (const float*)d_in[1];
    const void*  src = d_in[2];
    const void*  dst = d_in[3];

    int n_nodes = in_sizes[0] / 3;
    int n_edges = in_sizes[2];
    if (n_nodes > NMAX) n_nodes = NMAX;   // safety (problem fixed at 100k)

    const int TB = 256;
    int node_threads = (n_nodes + 3) / 4;
    int node_blocks  = (node_threads + TB - 1) / TB;
    int edge_threads = (n_edges + 3) / 4;
    int edge_blocks  = (edge_threads + TB - 1) / TB;

    prep_kernel<<<node_blocks, TB>>>(x, v, src, n_nodes, n_edges);
    edge_kernel<<<edge_blocks, TB>>>(src, dst, n_edges);
    finalize_kernel<<<node_blocks, TB>>>((float*)d_out, n_nodes);
}